// round 7
// baseline (speedup 1.0000x reference)
#include <cuda_runtime.h>

// Problem constants
#define Bn   2
#define Cc   64
#define Oo   64
#define Gg   16
#define Ee   128
#define Tin  512
#define Wk   7
#define Dd   4
#define Tout 256
#define FO   64
#define PER  264   // padded de-interleaved row length (floats)

// Per-block BN-stat partials: [o][j], j = b*64 + fo  (128 slots per channel)
__device__ float g_part1[Oo][128];
__device__ float g_part2[Oo][128];

// ---------------------------------------------------------------------------
// Conv + in-smem BN stats. Block = (b, g, fo), 2048 blocks, 128 threads.
// De-interleaved smem: pe[u] = pad[2u] (odd x samples), pos[u] = pad[2u-1]
// (even x samples); boundary slots are zero.
// Writes RAW pooled conv accumulator to out, and per-block stat partials
// (sum of w*x and w^2*x^2 over this block's rows) to g_part1/g_part2.
// ---------------------------------------------------------------------------
__global__ __launch_bounds__(128) void conv_stats_kernel(const float* __restrict__ x,
                                                         const float* __restrict__ wgt,
                                                         float* __restrict__ out) {
    __shared__ alignas(16) float pe[8][PER];
    __shared__ alignas(16) float pos[8][PER];
    __shared__ alignas(16) float ws[8][4][8];   // [w0..w6, 0]
    __shared__ float s_p1[4], s_p2[4];

    const int bid  = blockIdx.x;
    const int b    = bid >> 10;
    const int g    = (bid >> 6) & 15;
    const int fo   = bid & 63;
    const int tid  = threadIdx.x;
    const int lane = tid & 31;
    const int warp = tid >> 5;
    const int oc   = lane & 3;
    const int tc   = warp * 8 + (lane >> 2);   // 0..31; outputs t = 8tc..8tc+7

    if (tid < 4) { s_p1[tid] = 0.f; s_p2[tid] = 0.f; }

    // zero boundary slots {0,1,258..263} of each pe/pos row
    {
        int r  = tid >> 4;
        int s  = tid & 15;
        int ss = s & 7;
        int idx = (ss < 2) ? ss : (256 + ss);
        if (s < 8) pe[r][idx] = 0.f; else pos[r][idx] = 0.f;
    }

    // de-interleaving fill (coalesced LDG.128, conflict-free STS.64)
#pragma unroll
    for (int k = 0; k < 8; k++) {
        const int c = g * 4 + (k & 3);
        const int f = 2 * fo + (k >> 2);
        float4 v = reinterpret_cast<const float4*>(
            &x[((b * Cc + c) * Ee + f) * Tin])[tid];
        *reinterpret_cast<float2*>(&pe[k][2 * tid + 2])  = make_float2(v.y, v.w);
        *reinterpret_cast<float2*>(&pos[k][2 * tid + 2]) = make_float2(v.x, v.z);
    }

    // weights (taps padded to 8)
#pragma unroll
    for (int m = 0; m < 2; m++) {
        int j  = tid + 128 * m;
        int r  = j >> 5;
        int o2 = (j >> 3) & 3;
        int w  = j & 7;
        int d  = r & 3;
        int f2 = r >> 2;
        ws[r][o2][w] = (w < 7)
            ? wgt[(((g * 4 + o2) * Dd + d) * Ee + (2 * fo + f2)) * Wk + w] : 0.f;
    }
    __syncthreads();

    // ---- main conv: 8 outputs per thread (validated core) ----
    float acc[8];
#pragma unroll
    for (int j = 0; j < 8; j++) acc[j] = 0.f;

#pragma unroll
    for (int r = 0; r < 8; r++) {
        const float4* pe4  = reinterpret_cast<const float4*>(pe[r]);
        const float4* pos4 = reinterpret_cast<const float4*>(pos[r]);
        float E[12], S[12];
        *reinterpret_cast<float4*>(&E[0]) = pe4[2 * tc];
        *reinterpret_cast<float4*>(&E[4]) = pe4[2 * tc + 1];
        *reinterpret_cast<float4*>(&E[8]) = pe4[2 * tc + 2];
        *reinterpret_cast<float4*>(&S[0]) = pos4[2 * tc];
        *reinterpret_cast<float4*>(&S[4]) = pos4[2 * tc + 1];
        *reinterpret_cast<float4*>(&S[8]) = pos4[2 * tc + 2];
        float4 wA = *reinterpret_cast<const float4*>(&ws[r][oc][0]);
        float4 wB = *reinterpret_cast<const float4*>(&ws[r][oc][4]);
#pragma unroll
        for (int j = 0; j < 8; j++) {
            acc[j] = fmaf(wA.x, E[j],     acc[j]);
            acc[j] = fmaf(wA.y, S[j + 1], acc[j]);
            acc[j] = fmaf(wA.z, E[j + 1], acc[j]);
            acc[j] = fmaf(wA.w, S[j + 2], acc[j]);
            acc[j] = fmaf(wB.x, E[j + 2], acc[j]);
            acc[j] = fmaf(wB.y, S[j + 3], acc[j]);
            acc[j] = fmaf(wB.z, E[j + 3], acc[j]);
        }
    }

    // ---- raw accumulator store (affine applied later in place) ----
    {
        int ob = ((b * Oo + g * 4 + oc) * FO + fo) * Tout + 8 * tc;
        *reinterpret_cast<float4*>(&out[ob])     = make_float4(acc[0], acc[1], acc[2], acc[3]);
        *reinterpret_cast<float4*>(&out[ob + 4]) = make_float4(acc[4], acc[5], acc[6], acc[7]);
    }

    // ---- BN stats from smem: warp w handles rows 2w, 2w+1 ----
    const unsigned FULL = 0xffffffffu;
    float c1acc = 0.f, c2acc = 0.f;
#pragma unroll
    for (int rr = 0; rr < 2; rr++) {
        const int r = warp * 2 + rr;
        const float4* pe4  = reinterpret_cast<const float4*>(pe[r]);
        const float4* pos4 = reinterpret_cast<const float4*>(pos[r]);
        // so/so2: sums over odd x samples (pe), se/se2: even (pos).
        float so = 0.f, so2 = 0.f, se = 0.f, se2 = 0.f;
        float4 pa = pe4[lane],  pb = pe4[lane + 32];
        float4 qa = pos4[lane], qb = pos4[lane + 32];
        so += (pa.x + pa.y) + (pa.z + pa.w) + (pb.x + pb.y) + (pb.z + pb.w);
        so2 = fmaf(pa.x, pa.x, so2); so2 = fmaf(pa.y, pa.y, so2);
        so2 = fmaf(pa.z, pa.z, so2); so2 = fmaf(pa.w, pa.w, so2);
        so2 = fmaf(pb.x, pb.x, so2); so2 = fmaf(pb.y, pb.y, so2);
        so2 = fmaf(pb.z, pb.z, so2); so2 = fmaf(pb.w, pb.w, so2);
        se += (qa.x + qa.y) + (qa.z + qa.w) + (qb.x + qb.y) + (qb.z + qb.w);
        se2 = fmaf(qa.x, qa.x, se2); se2 = fmaf(qa.y, qa.y, se2);
        se2 = fmaf(qa.z, qa.z, se2); se2 = fmaf(qa.w, qa.w, se2);
        se2 = fmaf(qb.x, qb.x, se2); se2 = fmaf(qb.y, qb.y, se2);
        se2 = fmaf(qb.z, qb.z, se2); se2 = fmaf(qb.w, qb.w, se2);
        if (lane == 0) {
            float4 pc = pe4[64], qc = pos4[64];   // floats 256..259 (258,259 zero)
            so += pc.x + pc.y;
            so2 = fmaf(pc.x, pc.x, so2); so2 = fmaf(pc.y, pc.y, so2);
            se += qc.x + qc.y;
            se2 = fmaf(qc.x, qc.x, se2); se2 = fmaf(qc.y, qc.y, se2);
        }
#pragma unroll
        for (int off = 16; off > 0; off >>= 1) {
            so  += __shfl_xor_sync(FULL, so,  off);
            se  += __shfl_xor_sync(FULL, se,  off);
            so2 += __shfl_xor_sync(FULL, so2, off);
            se2 += __shfl_xor_sync(FULL, se2, off);
        }
        if (lane < 4) {
            // boundary samples: x0=pos[2], x1=pe[2], x509=pe[256],
            // x510=pos[257], x511=pe[257] (broadcast smem reads)
            float x0   = pos[r][2],  x1   = pe[r][2];
            float x509 = pe[r][256], x510 = pos[r][257], x511 = pe[r][257];
            float s1[7], s2[7];
            s1[0] = so - x509 - x511;  s2[0] = so2 - x509 * x509 - x511 * x511;
            s1[1] = se - x510;         s2[1] = se2 - x510 * x510;
            s1[2] = so - x511;         s2[2] = so2 - x511 * x511;
            s1[3] = se;                s2[3] = se2;
            s1[4] = so;                s2[4] = so2;
            s1[5] = se - x0;           s2[5] = se2 - x0 * x0;
            s1[6] = so - x1;           s2[6] = so2 - x1 * x1;
            const float* wr = &ws[r][lane][0];
#pragma unroll
            for (int w = 0; w < 7; w++) {
                float wv = wr[w];
                c1acc = fmaf(wv, s1[w], c1acc);
                c2acc = fmaf(wv * wv, s2[w], c2acc);
            }
        }
    }
    if (lane < 4) {
        atomicAdd(&s_p1[lane], c1acc);
        atomicAdd(&s_p2[lane], c2acc);
    }
    __syncthreads();
    if (tid < 4) {
        g_part1[g * 4 + tid][b * 64 + fo] = s_p1[tid];
        g_part2[g * 4 + tid][b * 64 + fo] = s_p2[tid];
    }
}

// ---------------------------------------------------------------------------
// Apply: inline finalize + affine + LeakyReLU, in place on out.
// Block = (b, o, q): 2*64*4 = 512 blocks, 256 threads, 4 float4/thread.
// Warp 0 reduces the 128 stat partials of channel o -> {a, bias} in smem.
// ---------------------------------------------------------------------------
__global__ __launch_bounds__(256) void apply_kernel(const float* __restrict__ gamma,
                                                    const float* __restrict__ beta,
                                                    float* __restrict__ out) {
    __shared__ float2 s_ab;

    const int bid  = blockIdx.x;
    const int b    = bid >> 8;
    const int o    = (bid >> 2) & 63;
    const int q    = bid & 3;
    const int tid  = threadIdx.x;
    const int lane = tid & 31;
    const int warp = tid >> 5;

    if (warp == 0) {
        float4 a4 = reinterpret_cast<const float4*>(g_part1[o])[lane];
        float4 b4 = reinterpret_cast<const float4*>(g_part2[o])[lane];
        float p1 = (a4.x + a4.y) + (a4.z + a4.w);
        float p2 = (b4.x + b4.y) + (b4.z + b4.w);
#pragma unroll
        for (int off = 16; off > 0; off >>= 1) {
            p1 += __shfl_xor_sync(0xffffffffu, p1, off);
            p2 += __shfl_xor_sync(0xffffffffu, p2, off);
        }
        if (lane == 0) {
            const float M = 1835008.f;   // B*D*E*t*W
            float mean = p1 / M;
            float var  = p2 / M - mean * mean;
            float a    = gamma[o] * rsqrtf(var + 1e-5f);
            s_ab = make_float2(a, 56.f * (beta[o] - mean * a));
        }
    }
    __syncthreads();

    const float2 ab = s_ab;
    float4* o4 = reinterpret_cast<float4*>(out);
    const int base = (b * Oo + o) * 4096 + q * 1024 + tid;   // float4 index

    float4 v[4];
#pragma unroll
    for (int k = 0; k < 4; k++) v[k] = o4[base + 256 * k];
#pragma unroll
    for (int k = 0; k < 4; k++) {
        float4 r;
        r.x = fmaf(ab.x, v[k].x, ab.y);
        r.y = fmaf(ab.x, v[k].y, ab.y);
        r.z = fmaf(ab.x, v[k].z, ab.y);
        r.w = fmaf(ab.x, v[k].w, ab.y);
        r.x = (r.x >= 0.f) ? r.x : 0.01f * r.x;
        r.y = (r.y >= 0.f) ? r.y : 0.01f * r.y;
        r.z = (r.z >= 0.f) ? r.z : 0.01f * r.z;
        r.w = (r.w >= 0.f) ? r.w : 0.01f * r.w;
        o4[base + 256 * k] = r;
    }
}

extern "C" void kernel_launch(void* const* d_in, const int* in_sizes, int n_in,
                              void* d_out, int out_size) {
    const float* x     = (const float*)d_in[0];
    const float* wgt   = (const float*)d_in[1];
    const float* gamma = (const float*)d_in[2];
    const float* beta  = (const float*)d_in[3];

    conv_stats_kernel<<<2048, 128>>>(x, wgt, (float*)d_out);
    apply_kernel<<<512, 256>>>(gamma, beta, (float*)d_out);
}

// round 8
// speedup vs baseline: 1.3036x; 1.3036x over previous
#include <cuda_runtime.h>

// Problem constants
#define Bn   2
#define Cc   64
#define Oo   64
#define Gg   16
#define Ee   128
#define Tin  512
#define Wk   7
#define Dd   4
#define Tout 256
#define FO   64
#define PER  264   // padded de-interleaved row length (floats)

// Per-block BN-stat partials: [o][j], j = b*32 + d*8 + fh  (64 slots)
__device__ float  g_part1[Oo][64];
__device__ float  g_part2[Oo][64];
__device__ float2 g_ab[Oo];           // {a, bias56}

// ---------------------------------------------------------------------------
// Stats kernel: grid (b, c, fh) = 2*64*8 = 1024 blocks, 256 threads.
// Warp handles 2 rows via 16-lane groups (gidx = lane>>4); lane sl = lane&15
// loads 8 float4 (MLP 8). 4-level butterfly within the group, boundary values
// via targeted shfl, per-lane (oc = sl<4) weight dot, one cross-group fold,
// 4 smem atomics per warp.
// ---------------------------------------------------------------------------
__global__ __launch_bounds__(256) void stats_kernel(const float* __restrict__ x,
                                                    const float* __restrict__ wgt) {
    __shared__ float s_p1[4], s_p2[4];

    const int bid  = blockIdx.x;
    const int b    = bid >> 9;
    const int c    = (bid >> 3) & 63;
    const int fh   = bid & 7;
    const int tid  = threadIdx.x;
    const int warp = tid >> 5;
    const int lane = tid & 31;
    const int sl   = lane & 15;
    const int gidx = lane >> 4;
    const int f    = fh * 16 + warp * 2 + gidx;

    if (tid < 4) { s_p1[tid] = 0.f; s_p2[tid] = 0.f; }
    __syncthreads();

    const float4* row = reinterpret_cast<const float4*>(
        &x[((b * Cc + c) * Ee + f) * Tin]);

    float4 v[8];
#pragma unroll
    for (int k = 0; k < 8; k++) v[k] = row[sl + 16 * k];

    float se = 0.f, so = 0.f, se2 = 0.f, so2 = 0.f;
#pragma unroll
    for (int k = 0; k < 8; k++) {
        float4 q = v[k];
        se += q.x + q.z;  so += q.y + q.w;
        se2 = fmaf(q.x, q.x, se2); se2 = fmaf(q.z, q.z, se2);
        so2 = fmaf(q.y, q.y, so2); so2 = fmaf(q.w, q.w, so2);
    }

    const unsigned FULL = 0xffffffffu;
    const int base = lane & ~15;
    // x0,x1 from lane sl=0 (float4 0); x509..x511 from lane sl=15 (float4 127)
    float x0   = __shfl_sync(FULL, v[0].x, base);
    float x1   = __shfl_sync(FULL, v[0].y, base);
    float x509 = __shfl_sync(FULL, v[7].y, base + 15);
    float x510 = __shfl_sync(FULL, v[7].z, base + 15);
    float x511 = __shfl_sync(FULL, v[7].w, base + 15);

#pragma unroll
    for (int off = 1; off < 16; off <<= 1) {
        se  += __shfl_xor_sync(FULL, se,  off);
        so  += __shfl_xor_sync(FULL, so,  off);
        se2 += __shfl_xor_sync(FULL, se2, off);
        so2 += __shfl_xor_sync(FULL, so2, off);
    }

    float c1 = 0.f, c2 = 0.f;
    if (sl < 4) {
        float s1[7], s2[7];
        s1[0] = so - x509 - x511;  s2[0] = so2 - x509 * x509 - x511 * x511;
        s1[1] = se - x510;         s2[1] = se2 - x510 * x510;
        s1[2] = so - x511;         s2[2] = so2 - x511 * x511;
        s1[3] = se;                s2[3] = se2;
        s1[4] = so;                s2[4] = so2;
        s1[5] = se - x0;           s2[5] = se2 - x0 * x0;
        s1[6] = so - x1;           s2[6] = so2 - x1 * x1;

        const int g = c >> 2, d = c & 3;
        const int o = g * 4 + sl;
        const float* wp = &wgt[((o * Dd + d) * Ee + f) * Wk];
#pragma unroll
        for (int w = 0; w < 7; w++) {
            float wv = wp[w];
            c1 = fmaf(wv, s1[w], c1);
            c2 = fmaf(wv * wv, s2[w], c2);
        }
    }
    // fold the 2 groups of the warp
    c1 += __shfl_xor_sync(FULL, c1, 16);
    c2 += __shfl_xor_sync(FULL, c2, 16);
    if (lane < 4) {
        atomicAdd(&s_p1[lane], c1);
        atomicAdd(&s_p2[lane], c2);
    }
    __syncthreads();
    if (tid < 4) {
        const int g = c >> 2, d = c & 3;
        const int j = b * 32 + d * 8 + fh;
        g_part1[g * 4 + tid][j] = s_p1[tid];
        g_part2[g * 4 + tid][j] = s_p2[tid];
    }
}

// ---------------------------------------------------------------------------
// Finalize: 1 block, 64 threads; thread o reduces its 64 partials, writes g_ab.
// ---------------------------------------------------------------------------
__global__ __launch_bounds__(64) void finalize_kernel(const float* __restrict__ gamma,
                                                      const float* __restrict__ beta) {
    const int o = threadIdx.x;
    const float4* p1v = reinterpret_cast<const float4*>(g_part1[o]);
    const float4* p2v = reinterpret_cast<const float4*>(g_part2[o]);
    float p1 = 0.f, p2 = 0.f;
#pragma unroll
    for (int k = 0; k < 16; k++) {
        float4 a = p1v[k], b = p2v[k];
        p1 += (a.x + a.y) + (a.z + a.w);
        p2 += (b.x + b.y) + (b.z + b.w);
    }
    const float M = 1835008.f;   // B*D*E*t*W
    float mean = p1 / M;
    float var  = p2 / M - mean * mean;
    float a    = gamma[o] * rsqrtf(var + 1e-5f);
    g_ab[o] = make_float2(a, 56.f * (beta[o] - mean * a));
}

// ---------------------------------------------------------------------------
// Fused conv + BN-affine + LeakyReLU (validated R5/R6 core). Block = (b,g,fo),
// 2048 blocks, 128 threads.
// ---------------------------------------------------------------------------
__global__ __launch_bounds__(128) void conv_kernel(const float* __restrict__ x,
                                                   const float* __restrict__ wgt,
                                                   float* __restrict__ out) {
    __shared__ alignas(16) float pe[8][PER];
    __shared__ alignas(16) float pos[8][PER];
    __shared__ alignas(16) float ws[8][4][8];   // [w0..w6, 0]

    const int bid  = blockIdx.x;
    const int b    = bid >> 10;
    const int g    = (bid >> 6) & 15;
    const int fo   = bid & 63;
    const int tid  = threadIdx.x;
    const int lane = tid & 31;
    const int warp = tid >> 5;
    const int oc   = lane & 3;
    const int tc   = warp * 8 + (lane >> 2);   // 0..31; outputs t = 8tc..8tc+7

    const float2 ab = g_ab[g * 4 + oc];

    // zero boundary slots {0,1,258..263} of each pe/pos row
    {
        int r  = tid >> 4;
        int s  = tid & 15;
        int ss = s & 7;
        int idx = (ss < 2) ? ss : (256 + ss);
        if (s < 8) pe[r][idx] = 0.f; else pos[r][idx] = 0.f;
    }

    // de-interleaving fill
#pragma unroll
    for (int k = 0; k < 8; k++) {
        const int c = g * 4 + (k & 3);
        const int f = 2 * fo + (k >> 2);
        float4 v = reinterpret_cast<const float4*>(
            &x[((b * Cc + c) * Ee + f) * Tin])[tid];
        *reinterpret_cast<float2*>(&pe[k][2 * tid + 2])  = make_float2(v.y, v.w);
        *reinterpret_cast<float2*>(&pos[k][2 * tid + 2]) = make_float2(v.x, v.z);
    }

    // weights
#pragma unroll
    for (int m = 0; m < 2; m++) {
        int j  = tid + 128 * m;
        int r  = j >> 5;
        int o2 = (j >> 3) & 3;
        int w  = j & 7;
        int d  = r & 3;
        int f2 = r >> 2;
        ws[r][o2][w] = (w < 7)
            ? wgt[(((g * 4 + o2) * Dd + d) * Ee + (2 * fo + f2)) * Wk + w] : 0.f;
    }
    __syncthreads();

    float acc[8];
#pragma unroll
    for (int j = 0; j < 8; j++) acc[j] = 0.f;

#pragma unroll
    for (int r = 0; r < 8; r++) {
        const float4* pe4  = reinterpret_cast<const float4*>(pe[r]);
        const float4* pos4 = reinterpret_cast<const float4*>(pos[r]);
        float E[12], S[12];
        *reinterpret_cast<float4*>(&E[0]) = pe4[2 * tc];
        *reinterpret_cast<float4*>(&E[4]) = pe4[2 * tc + 1];
        *reinterpret_cast<float4*>(&E[8]) = pe4[2 * tc + 2];
        *reinterpret_cast<float4*>(&S[0]) = pos4[2 * tc];
        *reinterpret_cast<float4*>(&S[4]) = pos4[2 * tc + 1];
        *reinterpret_cast<float4*>(&S[8]) = pos4[2 * tc + 2];
        float4 wA = *reinterpret_cast<const float4*>(&ws[r][oc][0]);
        float4 wB = *reinterpret_cast<const float4*>(&ws[r][oc][4]);
#pragma unroll
        for (int j = 0; j < 8; j++) {
            acc[j] = fmaf(wA.x, E[j],     acc[j]);
            acc[j] = fmaf(wA.y, S[j + 1], acc[j]);
            acc[j] = fmaf(wA.z, E[j + 1], acc[j]);
            acc[j] = fmaf(wA.w, S[j + 2], acc[j]);
            acc[j] = fmaf(wB.x, E[j + 2], acc[j]);
            acc[j] = fmaf(wB.y, S[j + 3], acc[j]);
            acc[j] = fmaf(wB.z, E[j + 3], acc[j]);
        }
    }

    {
        float r0[8];
#pragma unroll
        for (int j = 0; j < 8; j++) {
            float v = fmaf(ab.x, acc[j], ab.y);
            r0[j] = (v >= 0.f) ? v : 0.01f * v;
        }
        int ob = ((b * Oo + g * 4 + oc) * FO + fo) * Tout + 8 * tc;
        *reinterpret_cast<float4*>(&out[ob])     = make_float4(r0[0], r0[1], r0[2], r0[3]);
        *reinterpret_cast<float4*>(&out[ob + 4]) = make_float4(r0[4], r0[5], r0[6], r0[7]);
    }
}

extern "C" void kernel_launch(void* const* d_in, const int* in_sizes, int n_in,
                              void* d_out, int out_size) {
    const float* x     = (const float*)d_in[0];
    const float* wgt   = (const float*)d_in[1];
    const float* gamma = (const float*)d_in[2];
    const float* beta  = (const float*)d_in[3];

    stats_kernel<<<1024, 256>>>(x, wgt);
    finalize_kernel<<<1, 64>>>(gamma, beta);
    conv_kernel<<<2048, 128>>>(x, wgt, (float*)d_out);
}

// round 9
// speedup vs baseline: 1.3199x; 1.0125x over previous
#include <cuda_runtime.h>

// Problem constants
#define Bn   2
#define Cc   64
#define Oo   64
#define Gg   16
#define Ee   128
#define Tin  512
#define Wk   7
#define Dd   4
#define Tout 256
#define FO   64
#define PER  264   // padded de-interleaved row length (floats)

// Per-block BN-stat partials: [o][j], j = b*64 + fo  (128 slots per channel)
__device__ float  g_part1[Oo][128];
__device__ float  g_part2[Oo][128];
__device__ float2 g_ab[Oo];           // {a, bias56}

// ---------------------------------------------------------------------------
// Conv + in-register BN stats. Block = (b, g, fo), 2048 blocks, 128 threads.
// Fill: thread owns row rf = tid>>4 at float4 indices (tid&15)+16k, k=0..7;
// parity sums (se,so,se2,so2) accumulate in registers during the fill.
// Conv main loop = validated R5/R6 core; stores RAW accumulator to out.
// Stats: 4-level shfl within each 16-lane group, then 64 lanes do boundary
// corrections + weight dots -> smem atomics -> g_part.
// ---------------------------------------------------------------------------
__global__ __launch_bounds__(128) void conv_stats_kernel(const float* __restrict__ x,
                                                         const float* __restrict__ wgt,
                                                         float* __restrict__ out) {
    __shared__ alignas(16) float pe[8][PER];
    __shared__ alignas(16) float pos[8][PER];
    __shared__ alignas(16) float ws[8][4][8];   // [w0..w6, 0]
    __shared__ float s_p1[4], s_p2[4];

    const int bid  = blockIdx.x;
    const int b    = bid >> 10;
    const int g    = (bid >> 6) & 15;
    const int fo   = bid & 63;
    const int tid  = threadIdx.x;
    const int lane = tid & 31;
    const int warp = tid >> 5;
    const int oc   = lane & 3;
    const int tc   = warp * 8 + (lane >> 2);   // 0..31; outputs t = 8tc..8tc+7

    if (tid < 4) { s_p1[tid] = 0.f; s_p2[tid] = 0.f; }

    // zero boundary slots {0,1,258..263} of each pe/pos row
    {
        int r  = tid >> 4;
        int s  = tid & 15;
        int ss = s & 7;
        int idx = (ss < 2) ? ss : (256 + ss);
        if (s < 8) pe[r][idx] = 0.f; else pos[r][idx] = 0.f;
    }

    // weights (taps padded to 8) — LDGs issued before the fill
#pragma unroll
    for (int m = 0; m < 2; m++) {
        int j  = tid + 128 * m;
        int r  = j >> 5;
        int o2 = (j >> 3) & 3;
        int w  = j & 7;
        int d  = r & 3;
        int f2 = r >> 2;
        ws[r][o2][w] = (w < 7)
            ? wgt[(((g * 4 + o2) * Dd + d) * Ee + (2 * fo + f2)) * Wk + w] : 0.f;
    }

    // ---- fill (one row slice per thread) + in-register parity sums ----
    const int rf  = tid >> 4;          // row 0..7  (= warp*2 + (lane>>4))
    const int j16 = tid & 15;
    float se = 0.f, so = 0.f, se2 = 0.f, so2 = 0.f;
    {
        const int cf = g * 4 + (rf & 3);
        const int ff = 2 * fo + (rf >> 2);
        const float4* xrow = reinterpret_cast<const float4*>(
            &x[((b * Cc + cf) * Ee + ff) * Tin]);
#pragma unroll
        for (int k = 0; k < 8; k++) {
            int i = j16 + 16 * k;
            float4 v = xrow[i];
            *reinterpret_cast<float2*>(&pe[rf][2 * i + 2])  = make_float2(v.y, v.w);
            *reinterpret_cast<float2*>(&pos[rf][2 * i + 2]) = make_float2(v.x, v.z);
            se += v.x + v.z;  so += v.y + v.w;
            se2 = fmaf(v.x, v.x, se2); se2 = fmaf(v.z, v.z, se2);
            so2 = fmaf(v.y, v.y, so2); so2 = fmaf(v.w, v.w, so2);
        }
    }
    // reduce within the 16-lane group (stays inside the warp)
    const unsigned FULL = 0xffffffffu;
#pragma unroll
    for (int off = 1; off < 16; off <<= 1) {
        se  += __shfl_xor_sync(FULL, se,  off);
        so  += __shfl_xor_sync(FULL, so,  off);
        se2 += __shfl_xor_sync(FULL, se2, off);
        so2 += __shfl_xor_sync(FULL, so2, off);
    }
    __syncthreads();

    // ---- main conv: 8 outputs per thread (validated core) ----
    float acc[8];
#pragma unroll
    for (int j = 0; j < 8; j++) acc[j] = 0.f;

#pragma unroll
    for (int r = 0; r < 8; r++) {
        const float4* pe4  = reinterpret_cast<const float4*>(pe[r]);
        const float4* pos4 = reinterpret_cast<const float4*>(pos[r]);
        float E[12], S[12];
        *reinterpret_cast<float4*>(&E[0]) = pe4[2 * tc];
        *reinterpret_cast<float4*>(&E[4]) = pe4[2 * tc + 1];
        *reinterpret_cast<float4*>(&E[8]) = pe4[2 * tc + 2];
        *reinterpret_cast<float4*>(&S[0]) = pos4[2 * tc];
        *reinterpret_cast<float4*>(&S[4]) = pos4[2 * tc + 1];
        *reinterpret_cast<float4*>(&S[8]) = pos4[2 * tc + 2];
        float4 wA = *reinterpret_cast<const float4*>(&ws[r][oc][0]);
        float4 wB = *reinterpret_cast<const float4*>(&ws[r][oc][4]);
#pragma unroll
        for (int j = 0; j < 8; j++) {
            acc[j] = fmaf(wA.x, E[j],     acc[j]);
            acc[j] = fmaf(wA.y, S[j + 1], acc[j]);
            acc[j] = fmaf(wA.z, E[j + 1], acc[j]);
            acc[j] = fmaf(wA.w, S[j + 2], acc[j]);
            acc[j] = fmaf(wB.x, E[j + 2], acc[j]);
            acc[j] = fmaf(wB.y, S[j + 3], acc[j]);
            acc[j] = fmaf(wB.z, E[j + 3], acc[j]);
        }
    }

    // ---- raw accumulator store (affine applied in apply_kernel) ----
    {
        int ob = ((b * Oo + g * 4 + oc) * FO + fo) * Tout + 8 * tc;
        *reinterpret_cast<float4*>(&out[ob])     = make_float4(acc[0], acc[1], acc[2], acc[3]);
        *reinterpret_cast<float4*>(&out[ob + 4]) = make_float4(acc[4], acc[5], acc[6], acc[7]);
    }

    // ---- boundary corrections + weight dot (lanes with (lane&15) < 4) ----
    if (j16 < 4) {
        const int occ = j16;            // output channel within group
        // boundary samples of row rf (broadcast smem reads):
        // x0=pos[2], x1=pe[2], x509=pe[256], x510=pos[257], x511=pe[257]
        float x0   = pos[rf][2],  x1   = pe[rf][2];
        float x509 = pe[rf][256], x510 = pos[rf][257], x511 = pe[rf][257];
        float s1[7], s2[7];
        s1[0] = so - x509 - x511;  s2[0] = so2 - x509 * x509 - x511 * x511;
        s1[1] = se - x510;         s2[1] = se2 - x510 * x510;
        s1[2] = so - x511;         s2[2] = so2 - x511 * x511;
        s1[3] = se;                s2[3] = se2;
        s1[4] = so;                s2[4] = so2;
        s1[5] = se - x0;           s2[5] = se2 - x0 * x0;
        s1[6] = so - x1;           s2[6] = so2 - x1 * x1;
        const float* wr = &ws[rf][occ][0];
        float c1 = 0.f, c2 = 0.f;
#pragma unroll
        for (int w = 0; w < 7; w++) {
            float wv = wr[w];
            c1 = fmaf(wv, s1[w], c1);
            c2 = fmaf(wv * wv, s2[w], c2);
        }
        atomicAdd(&s_p1[occ], c1);
        atomicAdd(&s_p2[occ], c2);
    }
    __syncthreads();
    if (tid < 4) {
        g_part1[g * 4 + tid][b * 64 + fo] = s_p1[tid];
        g_part2[g * 4 + tid][b * 64 + fo] = s_p2[tid];
    }
}

// ---------------------------------------------------------------------------
// Finalize: 1 block, 64 threads; thread o reduces its 128 partials -> g_ab.
// ---------------------------------------------------------------------------
__global__ __launch_bounds__(64) void finalize_kernel(const float* __restrict__ gamma,
                                                      const float* __restrict__ beta) {
    const int o = threadIdx.x;
    const float4* p1v = reinterpret_cast<const float4*>(g_part1[o]);
    const float4* p2v = reinterpret_cast<const float4*>(g_part2[o]);
    float p1 = 0.f, p2 = 0.f;
#pragma unroll
    for (int k = 0; k < 32; k++) {
        float4 a = p1v[k], b = p2v[k];
        p1 += (a.x + a.y) + (a.z + a.w);
        p2 += (b.x + b.y) + (b.z + b.w);
    }
    const float M = 1835008.f;   // B*D*E*t*W
    float mean = p1 / M;
    float var  = p2 / M - mean * mean;
    float a    = gamma[o] * rsqrtf(var + 1e-5f);
    g_ab[o] = make_float2(a, 56.f * (beta[o] - mean * a));
}

// ---------------------------------------------------------------------------
// Apply: gateless in-place affine + LeakyReLU on out (L2-warm).
// Block = (b, o, q): 2*64*8 = 1024 blocks, 128 threads, 4 float4/thread.
// ---------------------------------------------------------------------------
__global__ __launch_bounds__(128) void apply_kernel(float* __restrict__ out) {
    const int bid = blockIdx.x;
    const int b   = bid >> 9;
    const int o   = (bid >> 3) & 63;
    const int q   = bid & 7;
    const int tid = threadIdx.x;

    const float2 ab = g_ab[o];
    float4* o4 = reinterpret_cast<float4*>(out);
    const int base = (b * Oo + o) * 4096 + q * 512 + tid;

    float4 v[4];
#pragma unroll
    for (int k = 0; k < 4; k++) v[k] = o4[base + 128 * k];
#pragma unroll
    for (int k = 0; k < 4; k++) {
        float4 r;
        r.x = fmaf(ab.x, v[k].x, ab.y);
        r.y = fmaf(ab.x, v[k].y, ab.y);
        r.z = fmaf(ab.x, v[k].z, ab.y);
        r.w = fmaf(ab.x, v[k].w, ab.y);
        r.x = (r.x >= 0.f) ? r.x : 0.01f * r.x;
        r.y = (r.y >= 0.f) ? r.y : 0.01f * r.y;
        r.z = (r.z >= 0.f) ? r.z : 0.01f * r.z;
        r.w = (r.w >= 0.f) ? r.w : 0.01f * r.w;
        o4[base + 128 * k] = r;
    }
}

extern "C" void kernel_launch(void* const* d_in, const int* in_sizes, int n_in,
                              void* d_out, int out_size) {
    const float* x     = (const float*)d_in[0];
    const float* wgt   = (const float*)d_in[1];
    const float* gamma = (const float*)d_in[2];
    const float* beta  = (const float*)d_in[3];

    conv_stats_kernel<<<2048, 128>>>(x, wgt, (float*)d_out);
    finalize_kernel<<<1, 64>>>(gamma, beta);
    apply_kernel<<<1024, 128>>>((float*)d_out);
}